// round 16
// baseline (speedup 1.0000x reference)
#include <cuda_runtime.h>
#include <cuda_bf16.h>
#include <cstdint>
#include <cstddef>

#define BB 8
#define TT 2048
#define DD 1024
#define HH 128
#define NTILES 16

#if defined(__CUDA_ARCH__) && (defined(__CUDA_ARCH_FEAT_SM103_ALL) || \
    defined(__CUDA_ARCH_FEAT_SM100_ALL) || defined(__CUDA_ARCH_SPECIFIC__) || \
    defined(__CUDA_ARCH_FAMILY_SPECIFIC__))
#define USE_TC 1
#else
#define USE_TC 0
#endif

__device__ __align__(1024) unsigned char g_Qimg[2][BB * NTILES][32768];
__device__ __align__(1024) unsigned char g_Kimg[2][BB * NTILES][32768];
__device__ __align__(1024) unsigned char g_VTimg[2][BB * NTILES][32768];
__device__ __align__(1024) unsigned char g_WTimg[3][2][262144];
__device__ float g_Q[BB * TT * HH];
__device__ float g_K[BB * TT * HH];
__device__ float g_V[BB * TT * HH];

__device__ __forceinline__ void cp_async16(void* s, const void* g) {
    unsigned sa = (unsigned)__cvta_generic_to_shared(s);
    asm volatile("cp.async.cg.shared.global [%0], [%1], 16;\n" :: "r"(sa), "l"(g));
}
#define CP_COMMIT() asm volatile("cp.async.commit_group;\n" ::: "memory")
#define CP_WAIT1()  asm volatile("cp.async.wait_group 1;\n" ::: "memory")
#define CP_WAIT0()  asm volatile("cp.async.wait_group 0;\n" ::: "memory")

__device__ __forceinline__ float truncbf(float x) {
    return __int_as_float(__float_as_int(x) & 0xffff0000);
}
__device__ __forceinline__ uint32_t prmt_hi(float e, float o) {
    uint32_t r;
    asm("prmt.b32 %0, %1, %2, 0x7632;" : "=r"(r) : "r"(__float_as_int(e)), "r"(__float_as_int(o)));
    return r;
}
__device__ __forceinline__ uint32_t pack2(float e, float o) {
    uint32_t r;
    asm("cvt.rn.bf16x2.f32 %0, %1, %2;" : "=r"(r) : "f"(o), "f"(e));
    return r;
}
__device__ __forceinline__ float ex2f(float x) {
    float r;
    asm("ex2.approx.f32 %0, %1;" : "=f"(r) : "f"(x));
    return r;
}
__device__ __forceinline__ int img_swz(int row, int col) {
    int byte = ((row >> 3) + (col >> 6) * 16) * 1024 + (row & 7) * 128 + ((col & 63) << 1);
    return byte ^ ((byte >> 3) & 0x70);
}
__device__ __forceinline__ int cimg_swz(int row, int col) {
    int byte = (row >> 3) * 1024 + (row & 7) * 128 + ((col & 63) << 1);
    return byte ^ ((byte >> 3) & 0x70);
}

struct AttnSmem {
    float Q[128][132];
    float KP[128][132];
    float V[128][132];
};

#if USE_TC
#define FENCE_PROXY() asm volatile("fence.proxy.async.shared::cta;" ::: "memory")
#define TC_WAIT_LD()  asm volatile("tcgen05.wait::ld.sync.aligned;" ::: "memory")
#define TC_WAIT_ST()  asm volatile("tcgen05.wait::st.sync.aligned;" ::: "memory")
#define TC_FENCE_BEFORE() asm volatile("tcgen05.fence::before_thread_sync;" ::: "memory")
#define TC_FENCE_AFTER()  asm volatile("tcgen05.fence::after_thread_sync;" ::: "memory")

__device__ __forceinline__ uint32_t smem_u32(const void* p) {
    return (uint32_t)__cvta_generic_to_shared(p);
}
__device__ __forceinline__ bool elect1() {
    uint32_t r;
    asm volatile("{\n\t.reg .pred p;\n\telect.sync _|p, 0xFFFFFFFF;\n\tselp.b32 %0,1,0,p;\n\t}" : "=r"(r));
    return r != 0;
}
__device__ __forceinline__ uint64_t mkdesc(const void* p) {
    const uint64_t base = (2ULL << 61) | (1ULL << 46) | (64ULL << 32) | (1ULL << 16);
    return base | ((uint64_t)(smem_u32(p) >> 4) & 0x3FFF);
}
__device__ __forceinline__ void mbar_init(uint32_t a, uint32_t c) {
    asm volatile("mbarrier.init.shared.b64 [%0], %1;" :: "r"(a), "r"(c) : "memory");
}
__device__ __forceinline__ void mbar_inval(uint32_t a) {
    asm volatile("mbarrier.inval.shared.b64 [%0];" :: "r"(a) : "memory");
}
__device__ __forceinline__ void mbar_wait(uint32_t a, uint32_t ph) {
    asm volatile(
        "{\n\t.reg .pred P;\n\tW%=:\n\t"
        "mbarrier.try_wait.parity.acquire.cta.shared::cta.b64 P, [%0], %1, 0x989680;\n\t"
        "@P bra.uni D%=;\n\tbra.uni W%=;\n\tD%=:\n\t}" :: "r"(a), "r"(ph) : "memory");
}
__device__ __forceinline__ void mma_ss(uint32_t d, uint64_t a, uint64_t b, uint32_t idesc, uint32_t en) {
    asm volatile(
        "{\n\t.reg .pred p;\n\tsetp.ne.u32 p, %4, 0;\n\t"
        "tcgen05.mma.cta_group::1.kind::f16 [%0], %1, %2, %3, {%5, %5, %5, %5}, p;\n\t}"
        :: "r"(d), "l"(a), "l"(b), "r"(idesc), "r"(en), "r"(0u) : "memory");
}
__device__ __forceinline__ void mma_ts(uint32_t d, uint32_t a, uint64_t b, uint32_t idesc, uint32_t en) {
    asm volatile(
        "{\n\t.reg .pred p;\n\tsetp.ne.u32 p, %4, 0;\n\t"
        "tcgen05.mma.cta_group::1.kind::f16 [%0], [%1], %2, %3, {%5, %5, %5, %5}, p;\n\t}"
        :: "r"(d), "r"(a), "l"(b), "r"(idesc), "r"(en), "r"(0u) : "memory");
}
__device__ __forceinline__ void tc_commit(uint32_t mbar) {
    asm volatile("tcgen05.commit.cta_group::1.mbarrier::arrive::one.shared::cluster.b64 [%0];"
                 :: "r"(mbar) : "memory");
}
#define LDTM32(r, a) \
    asm volatile( \
        "tcgen05.ld.sync.aligned.32x32b.x32.b32 " \
        "{%0, %1, %2, %3, %4, %5, %6, %7, %8, %9, %10, %11, %12, %13, %14, %15, " \
        " %16, %17, %18, %19, %20, %21, %22, %23, %24, %25, %26, %27, %28, %29, %30, %31}, [%32];" \
        : "=r"((r)[0]),  "=r"((r)[1]),  "=r"((r)[2]),  "=r"((r)[3]), \
          "=r"((r)[4]),  "=r"((r)[5]),  "=r"((r)[6]),  "=r"((r)[7]), \
          "=r"((r)[8]),  "=r"((r)[9]),  "=r"((r)[10]), "=r"((r)[11]), \
          "=r"((r)[12]), "=r"((r)[13]), "=r"((r)[14]), "=r"((r)[15]), \
          "=r"((r)[16]), "=r"((r)[17]), "=r"((r)[18]), "=r"((r)[19]), \
          "=r"((r)[20]), "=r"((r)[21]), "=r"((r)[22]), "=r"((r)[23]), \
          "=r"((r)[24]), "=r"((r)[25]), "=r"((r)[26]), "=r"((r)[27]), \
          "=r"((r)[28]), "=r"((r)[29]), "=r"((r)[30]), "=r"((r)[31]) \
        : "r"(a))
#define STTM32(a, r) \
    asm volatile( \
        "tcgen05.st.sync.aligned.32x32b.x32.b32 [%0], " \
        "{%1, %2, %3, %4, %5, %6, %7, %8, %9, %10, %11, %12, %13, %14, %15, %16, " \
        " %17, %18, %19, %20, %21, %22, %23, %24, %25, %26, %27, %28, %29, %30, %31, %32};" \
        :: "r"(a), \
           "r"((r)[0]),  "r"((r)[1]),  "r"((r)[2]),  "r"((r)[3]), \
           "r"((r)[4]),  "r"((r)[5]),  "r"((r)[6]),  "r"((r)[7]), \
           "r"((r)[8]),  "r"((r)[9]),  "r"((r)[10]), "r"((r)[11]), \
           "r"((r)[12]), "r"((r)[13]), "r"((r)[14]), "r"((r)[15]), \
           "r"((r)[16]), "r"((r)[17]), "r"((r)[18]), "r"((r)[19]), \
           "r"((r)[20]), "r"((r)[21]), "r"((r)[22]), "r"((r)[23]), \
           "r"((r)[24]), "r"((r)[25]), "r"((r)[26]), "r"((r)[27]), \
           "r"((r)[28]), "r"((r)[29]), "r"((r)[30]), "r"((r)[31]) \
        : "memory")

#define MMA_IDESC 0x8200490u
#define TM_S0 0
#define TM_S1 128
#define TM_PV 256
#define TM_PH 384
#define TM_PL 448
#endif // USE_TC

// ---------------------------------------------------------------------------
// Kernel 0: W -> W^T hi/lo images.  grid (3, 32).
// ---------------------------------------------------------------------------
__global__ __launch_bounds__(256) void wconv_kernel(
    const float* __restrict__ Wk, const float* __restrict__ Wq,
    const float* __restrict__ Wv)
{
#if USE_TC
    const int which = blockIdx.x;
    const int kbase = blockIdx.y * 32;
    const float* W = (which == 0) ? Wk : (which == 1) ? Wq : Wv;
    unsigned char* imgH = g_WTimg[which][0];
    unsigned char* imgL = g_WTimg[which][1];
    const int tid = threadIdx.x;
    for (int it = tid; it < 128 * 8; it += 256) {
        const int h  = it % 128;
        const int k0 = kbase + (it / 128) * 4;
        float f0 = W[(size_t)(k0 + 0) * HH + h];
        float f1 = W[(size_t)(k0 + 1) * HH + h];
        float f2 = W[(size_t)(k0 + 2) * HH + h];
        float f3 = W[(size_t)(k0 + 3) * HH + h];
        uint2 hv, lv;
        hv.x = prmt_hi(f0, f1); hv.y = prmt_hi(f2, f3);
        lv.x = pack2(f0 - truncbf(f0), f1 - truncbf(f1));
        lv.y = pack2(f2 - truncbf(f2), f3 - truncbf(f3));
        const int off = img_swz(h, k0);
        *(uint2*)(imgH + off) = hv;
        *(uint2*)(imgL + off) = lv;
    }
#endif
}

// ---------------------------------------------------------------------------
// Kernel 1: QKV projection — grid (128, 3): y = which (0=K, 1=Q, 2=V).
// 96KB smem/CTA -> 2 CTAs/SM; overhead of co-resident CTAs overlaps on the
// tensor pipe.  A (att or x) hi/lo double-buffered; W chunk single-buffered
// (loaded after MMA(c-1) wait; L2-hot).
// ---------------------------------------------------------------------------
__global__ __launch_bounds__(256, 2) void qkv_kernel(
    const float* __restrict__ att, const float* __restrict__ x,
    const float* __restrict__ Wk, const float* __restrict__ bk,
    const float* __restrict__ Wq, const float* __restrict__ bq,
    const float* __restrict__ Wv, const float* __restrict__ bv)
{
#if USE_TC
    extern __shared__ unsigned char dyn_raw[];
    unsigned char* base = (unsigned char*)((((uintptr_t)dyn_raw) + 1023) & ~(uintptr_t)1023);
    unsigned char* Ah[2] = { base,         base + 16384 };
    unsigned char* Al[2] = { base + 32768, base + 49152 };
    unsigned char* BH = base + 65536;
    unsigned char* BL = base + 81920;

    __shared__ uint32_t s_tmem;
    __shared__ __align__(8) unsigned long long s_mbar;

    const int which = blockIdx.y;           // 0=K, 1=Q, 2=V
    const int m0    = blockIdx.x * 128;
    const int blob  = blockIdx.x;
    const int tid   = threadIdx.x;
    const int wid   = tid / 32;
    const int lane  = tid % 32;

    const float* Asrc = (which == 2) ? x : att;
    const float* bias = (which == 0) ? bk : (which == 1) ? bq : bv;
    const unsigned char* wH = g_WTimg[which][0];
    const unsigned char* wL = g_WTimg[which][1];

    if (wid == 0)
        asm volatile("tcgen05.alloc.cta_group::1.sync.aligned.shared::cta.b32 [%0], %1;"
                     :: "r"(smem_u32(&s_tmem)), "r"(128u) : "memory");
    if (tid == 0) mbar_init(smem_u32(&s_mbar), 1);
    __syncthreads();
    const uint32_t tmem = s_tmem;
    const uint32_t mbar = smem_u32(&s_mbar);

    const int a_row = tid >> 1;
    const int a_sg  = (tid & 1) * 8;
    auto ldgA = [&](int c, float4 (&r)[8]) {
        const float* src = Asrc + (size_t)(m0 + a_row) * DD + c * 64 + a_sg * 4;
#pragma unroll
        for (int i = 0; i < 8; i++) r[i] = *(const float4*)(src + i * 4);
    };
    auto convA = [&](int buf, float4 (&r)[8]) {
#pragma unroll
        for (int i = 0; i < 8; i++) {
            const float4 v = r[i];
            uint2 hv, lv;
            hv.x = prmt_hi(v.x, v.y); hv.y = prmt_hi(v.z, v.w);
            lv.x = pack2(v.x - truncbf(v.x), v.y - truncbf(v.y));
            lv.y = pack2(v.z - truncbf(v.z), v.w - truncbf(v.w));
            const int off = cimg_swz(a_row, (a_sg + i) * 4);
            *(uint2*)(Ah[buf] + off) = hv;
            *(uint2*)(Al[buf] + off) = lv;
        }
    };
    auto loadB = [&](int c) {
        const int cb = c * 16384;
#pragma unroll
        for (int i = 0; i < 4; i++) {
            const int off = tid * 16 + i * 4096;
            cp_async16(BH + off, wH + cb + off);
            cp_async16(BL + off, wL + cb + off);
        }
        CP_COMMIT();
    };
    auto issueMMA = [&](int c) {
        const int buf = c & 1;
        const uint64_t aH = mkdesc(Ah[buf]), aL = mkdesc(Al[buf]);
        const uint64_t bH = mkdesc(BH), bL = mkdesc(BL);
#pragma unroll
        for (int p = 0; p < 3; p++) {
            uint64_t a, b;
            if (which <= 1) {               // D[token][h] = A_data x B_W
                a = (p == 1) ? aL : aH;
                b = (p == 2) ? bL : bH;
            } else {                        // D[h][token] = A_W x B_x
                a = (p == 2) ? bL : bH;
                b = (p == 1) ? aL : aH;
            }
#pragma unroll
            for (int k = 0; k < 4; k++)
                mma_ss(tmem, a + k * 2, b + k * 2, MMA_IDESC,
                       (c == 0 && p == 0 && k == 0) ? 0u : 1u);
        }
        tc_commit(mbar);
    };

    float4 ra0[8], ra1[8];
    int ph = 0;

    // prologue
    ldgA(0, ra0);
    ldgA(1, ra1);
    loadB(0);
    convA(0, ra0);
    FENCE_PROXY();
    CP_WAIT0();
    __syncthreads();

    // iter c: [wait MMA(c-1); loadB(c); drain]; sync; issue MMA(c);
    //         ldgA(c+2); convA(c+1)+fence.
    auto step = [&](int c, float4 (&rload)[8], float4 (&rconv)[8]) {
        if (c >= 1) {
            mbar_wait(mbar, ph & 1); ph++;  // MMA(c-1) done: B + A(c+1 buf) free
            loadB(c);
            CP_WAIT0();
        }
        __syncthreads();                    // all past wait before commit(c)
        if (wid == 0 && elect1()) issueMMA(c);
        if (c + 2 < 16) ldgA(c + 2, rload);
        if (c + 1 < 16) {
            convA((c + 1) & 1, rconv);
            FENCE_PROXY();
        }
    };

#pragma unroll 1
    for (int cc = 0; cc < 8; cc++) {
        step(2 * cc,     ra0, ra1);
        step(2 * cc + 1, ra1, ra0);
    }
    mbar_wait(mbar, ph & 1); ph++;          // MMA(15)
    TC_FENCE_AFTER();

    const int row     = (wid & 3) * 32 + lane;
    const int half    = (wid >= 4) ? 1 : 0;
    const int colhalf = half * 64;

    float d[64];
    LDTM32((uint32_t*)&d[0],  tmem + colhalf);
    LDTM32((uint32_t*)&d[32], tmem + colhalf + 32);
    TC_WAIT_LD();
    TC_FENCE_BEFORE();

    unsigned char* outH;
    unsigned char* outL;
    if (which == 0)      { outH = g_Kimg[0][blob];  outL = g_Kimg[1][blob]; }
    else if (which == 1) { outH = g_Qimg[0][blob];  outL = g_Qimg[1][blob]; }
    else                 { outH = g_VTimg[0][blob]; outL = g_VTimg[1][blob]; }

    if (which == 2) {
        const float bv_r = bias[row];
#pragma unroll
        for (int j = 0; j < 64; j++) d[j] += bv_r;
    } else if (which == 1) {
        const float sc = 16.322231186864473f;   // sqrt(128)*log2(e)
#pragma unroll
        for (int j = 0; j < 64; j++) d[j] = (d[j] + bias[colhalf + j]) * sc;
    } else {
#pragma unroll
        for (int j = 0; j < 64; j++) d[j] += bias[colhalf + j];
    }
#pragma unroll
    for (int cch = 0; cch < 8; cch++) {
        const float* sp = &d[8 * cch];
        uint4 hv, lv;
        hv.x = prmt_hi(sp[0], sp[1]); hv.y = prmt_hi(sp[2], sp[3]);
        hv.z = prmt_hi(sp[4], sp[5]); hv.w = prmt_hi(sp[6], sp[7]);
        lv.x = pack2(sp[0] - truncbf(sp[0]), sp[1] - truncbf(sp[1]));
        lv.y = pack2(sp[2] - truncbf(sp[2]), sp[3] - truncbf(sp[3]));
        lv.z = pack2(sp[4] - truncbf(sp[4]), sp[5] - truncbf(sp[5]));
        lv.w = pack2(sp[6] - truncbf(sp[6]), sp[7] - truncbf(sp[7]));
        const int off = img_swz(row, colhalf + 8 * cch);
        *(uint4*)(outH + off) = hv;
        *(uint4*)(outL + off) = lv;
    }

    __syncthreads();
    if (tid == 0) mbar_inval(mbar);
    __syncthreads();
    if (wid == 0) {
        asm volatile("tcgen05.relinquish_alloc_permit.cta_group::1.sync.aligned;");
        asm volatile("tcgen05.dealloc.cta_group::1.sync.aligned.b32 %0, %1;" :: "r"(tmem), "r"(128u));
    }

#else  // ---------------- fallback: FFMA QKV (grid (128,3)) ----------------
    extern __shared__ char smem_raw[];
    struct QkvSmemF {
        float As[2][128][20];
        float Ws[2][16][132];
    };
    QkvSmemF& smq = *reinterpret_cast<QkvSmemF*>(smem_raw);
    float (*As)[128][20] = smq.As;
    float (*Ws)[16][132] = smq.Ws;

    const int which = blockIdx.y;
    const float* A    = (which == 2) ? x  : att;
    const float* W    = (which == 0) ? Wk : (which == 1) ? Wq : Wv;
    const float* bias = (which == 0) ? bk : (which == 1) ? bq : bv;
    float* Out        = (which == 0) ? g_K : (which == 1) ? g_Q : g_V;

    const int tid = threadIdx.x;
    const int tx  = tid % 16;
    const int ty  = tid / 16;
    const int m0  = blockIdx.x * 128;

    float acc[8][8];
#pragma unroll
    for (int i = 0; i < 8; i++)
#pragma unroll
        for (int j = 0; j < 8; j++) acc[i][j] = 0.f;

    const int a_row0 = tid / 4,  a_c40 = tid % 4;
    const int a_row1 = (tid + 256) / 4, a_c41 = (tid + 256) % 4;
    const int w_r0 = tid / 32, w_c0 = tid % 32;
    const int w_r1 = (tid + 256) / 32, w_c1 = (tid + 256) % 32;

    float4 a_ld0, a_ld1, w_ld0, w_ld1;
    a_ld0 = *(const float4*)&A[(size_t)(m0 + a_row0) * DD + a_c40 * 4];
    a_ld1 = *(const float4*)&A[(size_t)(m0 + a_row1) * DD + a_c41 * 4];
    w_ld0 = *(const float4*)&W[(size_t)w_r0 * HH + w_c0 * 4];
    w_ld1 = *(const float4*)&W[(size_t)w_r1 * HH + w_c1 * 4];
    *(float4*)&As[0][a_row0][a_c40 * 4] = a_ld0;
    *(float4*)&As[0][a_row1][a_c41 * 4] = a_ld1;
    *(float4*)&Ws[0][w_r0][w_c0 * 4] = w_ld0;
    *(float4*)&Ws[0][w_r1][w_c1 * 4] = w_ld1;
    __syncthreads();

    for (int it = 0; it < DD / 16; it++) {
        const int cur = it & 1, nxt = cur ^ 1;
        if (it < DD / 16 - 1) {
            const int kt = (it + 1) * 16;
            a_ld0 = *(const float4*)&A[(size_t)(m0 + a_row0) * DD + kt + a_c40 * 4];
            a_ld1 = *(const float4*)&A[(size_t)(m0 + a_row1) * DD + kt + a_c41 * 4];
            w_ld0 = *(const float4*)&W[(size_t)(kt + w_r0) * HH + w_c0 * 4];
            w_ld1 = *(const float4*)&W[(size_t)(kt + w_r1) * HH + w_c1 * 4];
        }
#pragma unroll
        for (int kk4 = 0; kk4 < 4; kk4++) {
            float4 a4[8];
#pragma unroll
            for (int i = 0; i < 8; i++)
                a4[i] = *(const float4*)&As[cur][ty * 8 + i][kk4 * 4];
#pragma unroll
            for (int kkin = 0; kkin < 4; kkin++) {
                const int kk = kk4 * 4 + kkin;
                float4 w0v = *(const float4*)&Ws[cur][kk][tx * 4];
                float4 w1v = *(const float4*)&Ws[cur][kk][64 + tx * 4];
                const float* w0f = (const float*)&w0v;
                const float* w1f = (const float*)&w1v;
#pragma unroll
                for (int i = 0; i < 8; i++) {
                    const float a = ((const float*)&a4[i])[kkin];
#pragma unroll
                    for (int q = 0; q < 4; q++) {
                        acc[i][q]     += a * w0f[q];
                        acc[i][4 + q] += a * w1f[q];
                    }
                }
            }
        }
        if (it < DD / 16 - 1) {
            *(float4*)&As[nxt][a_row0][a_c40 * 4] = a_ld0;
            *(float4*)&As[nxt][a_row1][a_c41 * 4] = a_ld1;
            *(float4*)&Ws[nxt][w_r0][w_c0 * 4] = w_ld0;
            *(float4*)&Ws[nxt][w_r1][w_c1 * 4] = w_ld1;
            __syncthreads();
        }
    }

    float4 b0 = *(const float4*)&bias[tx * 4];
    float4 b1 = *(const float4*)&bias[64 + tx * 4];
#pragma unroll
    for (int i = 0; i < 8; i++) {
        float4 o0, o1;
        o0.x = acc[i][0] + b0.x; o0.y = acc[i][1] + b0.y;
        o0.z = acc[i][2] + b0.z; o0.w = acc[i][3] + b0.w;
        o1.x = acc[i][4] + b1.x; o1.y = acc[i][5] + b1.y;
        o1.z = acc[i][6] + b1.z; o1.w = acc[i][7] + b1.w;
        *(float4*)&Out[(size_t)(m0 + ty * 8 + i) * HH + tx * 4]      = o0;
        *(float4*)&Out[(size_t)(m0 + ty * 8 + i) * HH + 64 + tx * 4] = o1;
    }
#endif
}

// ---------------------------------------------------------------------------
// Kernel 2: attention — R14 config (lagged-PV + ex2, 2 syncs/tile; 139.6us).
// ---------------------------------------------------------------------------
__global__ __launch_bounds__(256) void attn_kernel(float* __restrict__ out)
{
#if USE_TC
    extern __shared__ unsigned char dyn_raw[];
    unsigned char* base = (unsigned char*)((((uintptr_t)dyn_raw) + 1023) & ~(uintptr_t)1023);
    unsigned char* sQh = base;
    unsigned char* sQl = base + 32768;
    unsigned char* sKh = base + 65536;
    unsigned char* sKl = base + 98304;
    unsigned char* sVh = base + 131072;
    unsigned char* sVl = base + 163840;

    __shared__ uint32_t s_tmem;
    __shared__ __align__(8) unsigned long long s_mbarS, s_mbarPV;
    __shared__ float redM[128][2];
    __shared__ float redS[128][2];

    const int b   = blockIdx.y;
    const int qt  = blockIdx.x;
    const int tid = threadIdx.x;
    const int wid = tid / 32;
    const int lane = tid % 32;
    const int row = (wid & 3) * 32 + lane;
    const int half = (wid >= 4) ? 1 : 0;
    const int colhalf = half * 64;
    const uint32_t warpoff = (uint32_t)(wid & 3) << 21;
    const int qblob = b * NTILES + qt;

    if (wid == 0)
        asm volatile("tcgen05.alloc.cta_group::1.sync.aligned.shared::cta.b32 [%0], %1;"
                     :: "r"(smem_u32(&s_tmem)), "r"(512u) : "memory");
    if (tid == 0) { mbar_init(smem_u32(&s_mbarS), 1); mbar_init(smem_u32(&s_mbarPV), 1); }
    __syncthreads();
    const uint32_t tmem = s_tmem;
    const uint32_t mbarS = smem_u32(&s_mbarS);
    const uint32_t mbarPV = smem_u32(&s_mbarPV);

    auto loadK_nc = [&](int kb) {
        const unsigned char* g0 = g_Kimg[0][kb];
        const unsigned char* g1 = g_Kimg[1][kb];
#pragma unroll
        for (int r = 0; r < 8; r++) {
            const int off = tid * 16 + r * 4096;
            cp_async16(sKh + off, g0 + off);
            cp_async16(sKl + off, g1 + off);
        }
    };
    auto loadV_nc = [&](int kb) {
        const unsigned char* g0 = g_VTimg[0][kb];
        const unsigned char* g1 = g_VTimg[1][kb];
#pragma unroll
        for (int r = 0; r < 8; r++) {
            const int off = tid * 16 + r * 4096;
            cp_async16(sVh + off, g0 + off);
            cp_async16(sVl + off, g1 + off);
        }
    };

    // prologue: Q + K0, one group
    {
        const unsigned char* gq0 = g_Qimg[0][qblob];
        const unsigned char* gq1 = g_Qimg[1][qblob];
#pragma unroll
        for (int r = 0; r < 8; r++) {
            const int off = tid * 16 + r * 4096;
            cp_async16(sQh + off, gq0 + off);
            cp_async16(sQl + off, gq1 + off);
        }
        loadK_nc(b * NTILES);
        CP_COMMIT();
    }

    const uint64_t dQh = mkdesc(sQh), dQl = mkdesc(sQl);
    const uint64_t dKh = mkdesc(sKh), dKl = mkdesc(sKl);
    const uint64_t dVh = mkdesc(sVh), dVl = mkdesc(sVl);

    auto issueS = [&](int t) {
        const uint32_t dst = tmem + ((t & 1) ? TM_S1 : TM_S0);
#pragma unroll
        for (int p = 0; p < 3; p++) {
            const uint64_t da = (p == 1) ? dQl : dQh;
            const uint64_t db = (p == 2) ? dKl : dKh;
#pragma unroll
            for (int k = 0; k < 8; k++) {
                const int koff = (k < 4) ? k * 2 : 1024 + (k - 4) * 2;
                mma_ss(dst, da + koff, db + koff, MMA_IDESC, (p == 0 && k == 0) ? 0u : 1u);
            }
        }
        tc_commit(mbarS);
    };
    auto issuePV = [&]() {
#pragma unroll
        for (int p = 0; p < 3; p++) {
            const uint32_t abase = tmem + ((p == 1) ? TM_PL : TM_PH);
            const uint64_t db = (p == 2) ? dVl : dVh;
#pragma unroll
            for (int k = 0; k < 8; k++) {
                const int koff = (k < 4) ? k * 2 : 1024 + (k - 4) * 2;
                mma_ts(tmem + TM_PV, abase + k * 8, db + koff, MMA_IDESC,
                       (p == 0 && k == 0) ? 0u : 1u);
            }
        }
        tc_commit(mbarPV);
    };

    float O[64];
#pragma unroll
    for (int j = 0; j < 64; j++) O[j] = 0.f;
    float m_r = -1e30f, l_r = 0.f, corr_prev = 1.f;
    int phS = 0, phPV = 0;

    CP_WAIT0();               // Q + K0 resident
    FENCE_PROXY();
    __syncthreads();
    if (wid == 0 && elect1()) issueS(0);

    for (int t = 0; t < NTILES; t++) {
        mbar_wait(mbarS, phS & 1); phS++;   // S(t) done => PV(t-1) done (queue)

        if (t + 1 < NTILES) loadK_nc(b * NTILES + t + 1);
        loadV_nc(b * NTILES + t);
        CP_COMMIT();

        TC_FENCE_AFTER();
        if (t >= 1) {
            mbar_wait(mbarPV, phPV & 1); phPV++;
            TC_FENCE_AFTER();
            float d[64];
            LDTM32((uint32_t*)&d[0],  tmem + TM_PV + colhalf);
            LDTM32((uint32_t*)&d[32], tmem + TM_PV + colhalf + 32);
            TC_WAIT_LD();
#pragma unroll
            for (int j = 0; j < 64; j++) O[j] = O[j] * corr_prev + d[j];
        }

        float s[64];
        const uint32_t sbase = tmem + ((t & 1) ? TM_S1 : TM_S0) + colhalf;
        LDTM32((uint32_t*)&s[0],  sbase);
        LDTM32((uint32_t*)&s[32], sbase + 32);
        TC_WAIT_LD();

        float mx = s[0];
#pragma unroll
        for (int j = 1; j < 64; j++) mx = fmaxf(mx, s[j]);
        redM[row][half] = mx;
        __syncthreads();                    // sync 1
        const float mtile = fmaxf(redM[row][0], redM[row][1]);
        const float mnew = fmaxf(m_r, mtile);
        const float corr = ex2f(m_r - mnew);
        m_r = mnew;
        float lsum = 0.f;
#pragma unroll
        for (int j = 0; j < 64; j++) {
            const float p = ex2f(s[j] - mnew);
            s[j] = p;
            lsum += p;
        }
        redS[row][half] = lsum;

        uint32_t phx[32], plx[32];
#pragma unroll
        for (int j = 0; j < 32; j++) {
            const float e = s[2 * j], o = s[2 * j + 1];
            phx[j] = prmt_hi(e, o);
            plx[j] = pack2(e - truncbf(e), o - truncbf(o));
        }
        STTM32(tmem + TM_PH + 32 * half + warpoff, phx);
        STTM32(tmem + TM_PL + 32 * half + warpoff, plx);
        TC_WAIT_ST();
        TC_FENCE_BEFORE();

        CP_WAIT0();
        __syncthreads();                    // sync 2
        l_r = l_r * corr + redS[row][0] + redS[row][1];
        corr_prev = corr;

        if (wid == 0 && elect1()) {
            TC_FENCE_AFTER();
            issuePV();
            if (t + 1 < NTILES) issueS(t + 1);
        }
    }

    mbar_wait(mbarPV, phPV & 1); phPV++;
    TC_FENCE_AFTER();
    {
        float d[64];
        LDTM32((uint32_t*)&d[0],  tmem + TM_PV + colhalf);
        LDTM32((uint32_t*)&d[32], tmem + TM_PV + colhalf + 32);
        TC_WAIT_LD();
        TC_FENCE_BEFORE();
#pragma unroll
        for (int j = 0; j < 64; j++) O[j] = O[j] * corr_prev + d[j];
    }

    const float inv = 1.f / l_r;
    const size_t obase = ((size_t)b * TT + (size_t)qt * 128 + row) * HH + colhalf;
#pragma unroll
    for (int j4 = 0; j4 < 16; j4++) {
        float4 o;
        o.x = O[4 * j4 + 0] * inv; o.y = O[4 * j4 + 1] * inv;
        o.z = O[4 * j4 + 2] * inv; o.w = O[4 * j4 + 3] * inv;
        *(float4*)&out[obase + 4 * j4] = o;
    }

    __syncthreads();
    if (tid == 0) { mbar_inval(mbarS); mbar_inval(mbarPV); }
    __syncthreads();
    if (wid == 0) {
        asm volatile("tcgen05.relinquish_alloc_permit.cta_group::1.sync.aligned;");
        asm volatile("tcgen05.dealloc.cta_group::1.sync.aligned.b32 %0, %1;" :: "r"(tmem), "r"(512u));
    }

#else  // ---------------- fallback: fp32 FFMA flash attention ----------------
    extern __shared__ char smem_raw[];
    AttnSmem& sm = *reinterpret_cast<AttnSmem*>(smem_raw);

    const int b  = blockIdx.y;
    const int q0 = blockIdx.x * 128;
    const float scale = 11.313708498984761f;

    const int tid = threadIdx.x;
    const int tx  = tid % 16;
    const int ty  = tid / 16;

    const float* Qg = g_Q + ((size_t)b * TT + q0) * HH;
#pragma unroll
    for (int r = 0; r < 16; r++) {
        const int idx = tid + r * 256;
        const int row = idx / 32, c4 = idx % 32;
        float4 v = *(const float4*)&Qg[(size_t)row * HH + c4 * 4];
        v.x *= scale; v.y *= scale; v.z *= scale; v.w *= scale;
        *(float4*)&sm.Q[row][c4 * 4] = v;
    }

    float O[8][8];
    float m_r[8], l_r[8];
#pragma unroll
    for (int i = 0; i < 8; i++) {
        m_r[i] = -1e30f; l_r[i] = 0.f;
#pragma unroll
        for (int j = 0; j < 8; j++) O[i][j] = 0.f;
    }
    __syncthreads();

    for (int k0 = 0; k0 < TT; k0 += 128) {
        const float* Kg = g_K + ((size_t)b * TT + k0) * HH;
        const float* Vg = g_V + ((size_t)b * TT + k0) * HH;

#pragma unroll
        for (int r = 0; r < 16; r++) {
            const int idx = tid + r * 256;
            const int row = idx / 32, c4 = idx % 32;
            cp_async16(&sm.KP[row][c4 * 4], &Kg[(size_t)row * HH + c4 * 4]);
        }
        CP_COMMIT();
#pragma unroll
        for (int r = 0; r < 16; r++) {
            const int idx = tid + r * 256;
            const int row = idx / 32, c4 = idx % 32;
            cp_async16(&sm.V[row][c4 * 4], &Vg[(size_t)row * HH + c4 * 4]);
        }
        CP_COMMIT();

        CP_WAIT1();
        __syncthreads();

        float s[8][8];
#pragma unroll
        for (int i = 0; i < 8; i++)
#pragma unroll
            for (int j = 0; j < 8; j++) s[i][j] = 0.f;

#pragma unroll 8
        for (int kk4 = 0; kk4 < 32; kk4++) {
            float4 q4[8];
#pragma unroll
            for (int i = 0; i < 8; i++)
                q4[i] = *(const float4*)&sm.Q[ty * 8 + i][kk4 * 4];
#pragma unroll
            for (int j = 0; j < 8; j++) {
                float4 k4 = *(const float4*)&sm.KP[tx + 16 * j][kk4 * 4];
#pragma unroll
                for (int i = 0; i < 8; i++) {
                    s[i][j] += q4[i].x * k4.x + q4[i].y * k4.y
                             + q4[i].z * k4.z + q4[i].w * k4.w;
                }
            }
        }
        __syncthreads();

#pragma unroll
        for (int i = 0; i < 8; i++) {
            float mx = s[i][0];
#pragma unroll
            for (int j = 1; j < 8; j++) mx = fmaxf(mx, s[i][j]);
#pragma unroll
            for (int o = 1; o < 16; o <<= 1)
                mx = fmaxf(mx, __shfl_xor_sync(0xffffffffu, mx, o));
            const float mnew = fmaxf(m_r[i], mx);
            const float corr = __expf(m_r[i] - mnew);
            m_r[i] = mnew;
            float sum = 0.f;
#pragma unroll
            for (int j = 0; j < 8; j++) {
                const float p = __expf(s[i][j] - mnew);
                s[i][j] = p;
                sum += p;
            }
#pragma unroll
            for (int o = 1; o < 16; o <<= 1)
                sum += __shfl_xor_sync(0xffffffffu, sum, o);
            l_r[i] = l_r[i] * corr + sum;
#pragma unroll
            for (int j = 0; j < 8; j++) O[i][j] *= corr;
        }

#pragma unroll
        for (int i = 0; i < 8; i++)
#pragma unroll
            for (int j = 0; j < 8; j++)
                sm.KP[ty * 8 + i][tx + 16 * j] = s[i][j];

        CP_WAIT0();
        __syncthreads();

#pragma unroll 4
        for (int k4 = 0; k4 < 32; k4++) {
            float4 p4[8];
#pragma unroll
            for (int i = 0; i < 8; i++)
                p4[i] = *(const float4*)&sm.KP[ty * 8 + i][k4 * 4];
#pragma unroll
            for (int kk = 0; kk < 4; kk++) {
                const int k = k4 * 4 + kk;
                float4 v0 = *(const float4*)&sm.V[k][tx * 4];
                float4 v1 = *(const float4*)&sm.V[k][64 + tx * 4];
                const float* v0f = (const float*)&v0;
                const float* v1f = (const float*)&v1;
#pragma unroll
                for (int i = 0; i < 8; i++) {
                    const float p = ((const float*)&p4[i])[kk];
#pragma unroll
                    for (int q = 0; q < 4; q++) {
                        O[i][q]     += p * v0f[q];
                        O[i][4 + q] += p * v1f[q];
                    }
                }
            }
        }
        __syncthreads();
    }

#pragma unroll
    for (int i = 0; i < 8; i++) {
        const float inv = 1.f / l_r[i];
        float4 o0, o1;
        o0.x = O[i][0] * inv; o0.y = O[i][1] * inv;
        o0.z = O[i][2] * inv; o0.w = O[i][3] * inv;
        o1.x = O[i][4] * inv; o1.y = O[i][5] * inv;
        o1.z = O[i][6] * inv; o1.w = O[i][7] * inv;
        const size_t base = ((size_t)b * TT + q0 + ty * 8 + i) * HH;
        *(float4*)&out[base + tx * 4]      = o0;
        *(float4*)&out[base + 64 + tx * 4] = o1;
    }
#endif
}

// ---------------------------------------------------------------------------
extern "C" void kernel_launch(void* const* d_in, const int* in_sizes, int n_in,
                              void* d_out, int out_size)
{
    const float* x   = (const float*)d_in[0];
    const float* att = (const float*)d_in[1];
    const float* Wk  = (const float*)d_in[2];
    const float* bk  = (const float*)d_in[3];
    const float* Wq  = (const float*)d_in[4];
    const float* bq  = (const float*)d_in[5];
    const float* Wv  = (const float*)d_in[6];
    const float* bv  = (const float*)d_in[7];
    float* out = (float*)d_out;
    (void)in_sizes; (void)n_in; (void)out_size;

    wconv_kernel<<<dim3(3, 32), 256>>>(Wk, Wq, Wv);

    const int qkv_smem = 98304 + 2048;      // 96KB + align -> 2 CTAs/SM
    cudaFuncSetAttribute(qkv_kernel,
                         cudaFuncAttributeMaxDynamicSharedMemorySize, qkv_smem);
    qkv_kernel<<<dim3(BB * NTILES, 3), 256, qkv_smem>>>(att, x, Wk, bk, Wq, bq, Wv, bv);

    const int attn_smem = (int)sizeof(AttnSmem);
    cudaFuncSetAttribute(attn_kernel,
                         cudaFuncAttributeMaxDynamicSharedMemorySize, attn_smem);
    attn_kernel<<<dim3(NTILES, BB), 256, attn_smem>>>(out);
}

// round 17
// speedup vs baseline: 1.3588x; 1.3588x over previous
#include <cuda_runtime.h>
#include <cuda_bf16.h>
#include <cstdint>
#include <cstddef>

#define BB 8
#define TT 2048
#define DD 1024
#define HH 128
#define NTILES 16

#if defined(__CUDA_ARCH__) && (defined(__CUDA_ARCH_FEAT_SM103_ALL) || \
    defined(__CUDA_ARCH_FEAT_SM100_ALL) || defined(__CUDA_ARCH_SPECIFIC__) || \
    defined(__CUDA_ARCH_FAMILY_SPECIFIC__))
#define USE_TC 1
#else
#define USE_TC 0
#endif

__device__ __align__(1024) unsigned char g_Qimg[2][BB * NTILES][32768];
__device__ __align__(1024) unsigned char g_Kimg[2][BB * NTILES][32768];
__device__ __align__(1024) unsigned char g_VTimg[2][BB * NTILES][32768];
__device__ __align__(1024) unsigned char g_WTimg[3][2][262144];
__device__ float g_Q[BB * TT * HH];
__device__ float g_K[BB * TT * HH];
__device__ float g_V[BB * TT * HH];

__device__ __forceinline__ void cp_async16(void* s, const void* g) {
    unsigned sa = (unsigned)__cvta_generic_to_shared(s);
    asm volatile("cp.async.cg.shared.global [%0], [%1], 16;\n" :: "r"(sa), "l"(g));
}
#define CP_COMMIT() asm volatile("cp.async.commit_group;\n" ::: "memory")
#define CP_WAIT1()  asm volatile("cp.async.wait_group 1;\n" ::: "memory")
#define CP_WAIT0()  asm volatile("cp.async.wait_group 0;\n" ::: "memory")

__device__ __forceinline__ float truncbf(float x) {
    return __int_as_float(__float_as_int(x) & 0xffff0000);
}
__device__ __forceinline__ uint32_t prmt_hi(float e, float o) {
    uint32_t r;
    asm("prmt.b32 %0, %1, %2, 0x7632;" : "=r"(r) : "r"(__float_as_int(e)), "r"(__float_as_int(o)));
    return r;
}
__device__ __forceinline__ uint32_t pack2(float e, float o) {
    uint32_t r;
    asm("cvt.rn.bf16x2.f32 %0, %1, %2;" : "=r"(r) : "f"(o), "f"(e));
    return r;
}
__device__ __forceinline__ float ex2f(float x) {
    float r;
    asm("ex2.approx.f32 %0, %1;" : "=f"(r) : "f"(x));
    return r;
}
__device__ __forceinline__ int img_swz(int row, int col) {
    int byte = ((row >> 3) + (col >> 6) * 16) * 1024 + (row & 7) * 128 + ((col & 63) << 1);
    return byte ^ ((byte >> 3) & 0x70);
}
__device__ __forceinline__ int cimg_swz(int row, int col) {
    int byte = (row >> 3) * 1024 + (row & 7) * 128 + ((col & 63) << 1);
    return byte ^ ((byte >> 3) & 0x70);
}

struct AttnSmem {
    float Q[128][132];
    float KP[128][132];
    float V[128][132];
};

#if USE_TC
#define FENCE_PROXY() asm volatile("fence.proxy.async.shared::cta;" ::: "memory")
#define TC_WAIT_LD()  asm volatile("tcgen05.wait::ld.sync.aligned;" ::: "memory")
#define TC_WAIT_ST()  asm volatile("tcgen05.wait::st.sync.aligned;" ::: "memory")
#define TC_FENCE_BEFORE() asm volatile("tcgen05.fence::before_thread_sync;" ::: "memory")
#define TC_FENCE_AFTER()  asm volatile("tcgen05.fence::after_thread_sync;" ::: "memory")

__device__ __forceinline__ uint32_t smem_u32(const void* p) {
    return (uint32_t)__cvta_generic_to_shared(p);
}
__device__ __forceinline__ bool elect1() {
    uint32_t r;
    asm volatile("{\n\t.reg .pred p;\n\telect.sync _|p, 0xFFFFFFFF;\n\tselp.b32 %0,1,0,p;\n\t}" : "=r"(r));
    return r != 0;
}
__device__ __forceinline__ uint64_t mkdesc(const void* p) {
    const uint64_t base = (2ULL << 61) | (1ULL << 46) | (64ULL << 32) | (1ULL << 16);
    return base | ((uint64_t)(smem_u32(p) >> 4) & 0x3FFF);
}
__device__ __forceinline__ void mbar_init(uint32_t a, uint32_t c) {
    asm volatile("mbarrier.init.shared.b64 [%0], %1;" :: "r"(a), "r"(c) : "memory");
}
__device__ __forceinline__ void mbar_inval(uint32_t a) {
    asm volatile("mbarrier.inval.shared.b64 [%0];" :: "r"(a) : "memory");
}
__device__ __forceinline__ void mbar_wait(uint32_t a, uint32_t ph) {
    asm volatile(
        "{\n\t.reg .pred P;\n\tW%=:\n\t"
        "mbarrier.try_wait.parity.acquire.cta.shared::cta.b64 P, [%0], %1, 0x989680;\n\t"
        "@P bra.uni D%=;\n\tbra.uni W%=;\n\tD%=:\n\t}" :: "r"(a), "r"(ph) : "memory");
}
__device__ __forceinline__ void mma_ss(uint32_t d, uint64_t a, uint64_t b, uint32_t idesc, uint32_t en) {
    asm volatile(
        "{\n\t.reg .pred p;\n\tsetp.ne.u32 p, %4, 0;\n\t"
        "tcgen05.mma.cta_group::1.kind::f16 [%0], %1, %2, %3, {%5, %5, %5, %5}, p;\n\t}"
        :: "r"(d), "l"(a), "l"(b), "r"(idesc), "r"(en), "r"(0u) : "memory");
}
__device__ __forceinline__ void mma_ts(uint32_t d, uint32_t a, uint64_t b, uint32_t idesc, uint32_t en) {
    asm volatile(
        "{\n\t.reg .pred p;\n\tsetp.ne.u32 p, %4, 0;\n\t"
        "tcgen05.mma.cta_group::1.kind::f16 [%0], [%1], %2, %3, {%5, %5, %5, %5}, p;\n\t}"
        :: "r"(d), "r"(a), "l"(b), "r"(idesc), "r"(en), "r"(0u) : "memory");
}
__device__ __forceinline__ void tc_commit(uint32_t mbar) {
    asm volatile("tcgen05.commit.cta_group::1.mbarrier::arrive::one.shared::cluster.b64 [%0];"
                 :: "r"(mbar) : "memory");
}
#define LDTM32(r, a) \
    asm volatile( \
        "tcgen05.ld.sync.aligned.32x32b.x32.b32 " \
        "{%0, %1, %2, %3, %4, %5, %6, %7, %8, %9, %10, %11, %12, %13, %14, %15, " \
        " %16, %17, %18, %19, %20, %21, %22, %23, %24, %25, %26, %27, %28, %29, %30, %31}, [%32];" \
        : "=r"((r)[0]),  "=r"((r)[1]),  "=r"((r)[2]),  "=r"((r)[3]), \
          "=r"((r)[4]),  "=r"((r)[5]),  "=r"((r)[6]),  "=r"((r)[7]), \
          "=r"((r)[8]),  "=r"((r)[9]),  "=r"((r)[10]), "=r"((r)[11]), \
          "=r"((r)[12]), "=r"((r)[13]), "=r"((r)[14]), "=r"((r)[15]), \
          "=r"((r)[16]), "=r"((r)[17]), "=r"((r)[18]), "=r"((r)[19]), \
          "=r"((r)[20]), "=r"((r)[21]), "=r"((r)[22]), "=r"((r)[23]), \
          "=r"((r)[24]), "=r"((r)[25]), "=r"((r)[26]), "=r"((r)[27]), \
          "=r"((r)[28]), "=r"((r)[29]), "=r"((r)[30]), "=r"((r)[31]) \
        : "r"(a))
#define STTM32(a, r) \
    asm volatile( \
        "tcgen05.st.sync.aligned.32x32b.x32.b32 [%0], " \
        "{%1, %2, %3, %4, %5, %6, %7, %8, %9, %10, %11, %12, %13, %14, %15, %16, " \
        " %17, %18, %19, %20, %21, %22, %23, %24, %25, %26, %27, %28, %29, %30, %31, %32};" \
        :: "r"(a), \
           "r"((r)[0]),  "r"((r)[1]),  "r"((r)[2]),  "r"((r)[3]), \
           "r"((r)[4]),  "r"((r)[5]),  "r"((r)[6]),  "r"((r)[7]), \
           "r"((r)[8]),  "r"((r)[9]),  "r"((r)[10]), "r"((r)[11]), \
           "r"((r)[12]), "r"((r)[13]), "r"((r)[14]), "r"((r)[15]), \
           "r"((r)[16]), "r"((r)[17]), "r"((r)[18]), "r"((r)[19]), \
           "r"((r)[20]), "r"((r)[21]), "r"((r)[22]), "r"((r)[23]), \
           "r"((r)[24]), "r"((r)[25]), "r"((r)[26]), "r"((r)[27]), \
           "r"((r)[28]), "r"((r)[29]), "r"((r)[30]), "r"((r)[31]) \
        : "memory")

#define MMA_IDESC 0x8200490u
#define TM_S0 0
#define TM_S1 128
#define TM_PV 256
#define TM_PH 384
#define TM_PL 448
#endif // USE_TC

// ---------------------------------------------------------------------------
// Kernel 0: W -> W^T hi/lo images.  grid (3, 64): finer K split (16 cols).
// ---------------------------------------------------------------------------
__global__ __launch_bounds__(256) void wconv_kernel(
    const float* __restrict__ Wk, const float* __restrict__ Wq,
    const float* __restrict__ Wv)
{
#if USE_TC
    const int which = blockIdx.x;
    const int kbase = blockIdx.y * 16;
    const float* W = (which == 0) ? Wk : (which == 1) ? Wq : Wv;
    unsigned char* imgH = g_WTimg[which][0];
    unsigned char* imgL = g_WTimg[which][1];
    const int tid = threadIdx.x;
    for (int it = tid; it < 128 * 4; it += 256) {
        const int h  = it % 128;
        const int k0 = kbase + (it / 128) * 4;
        float f0 = W[(size_t)(k0 + 0) * HH + h];
        float f1 = W[(size_t)(k0 + 1) * HH + h];
        float f2 = W[(size_t)(k0 + 2) * HH + h];
        float f3 = W[(size_t)(k0 + 3) * HH + h];
        uint2 hv, lv;
        hv.x = prmt_hi(f0, f1); hv.y = prmt_hi(f2, f3);
        lv.x = pack2(f0 - truncbf(f0), f1 - truncbf(f1));
        lv.y = pack2(f2 - truncbf(f2), f3 - truncbf(f3));
        const int off = img_swz(h, k0);
        *(uint2*)(imgH + off) = hv;
        *(uint2*)(imgL + off) = lv;
    }
#endif
}

// ---------------------------------------------------------------------------
// Kernel 1: QKV projection — R14-proven pipeline (wait at top, loadB(c+1),
// one sync per chunk).  grid (128, 2): y0 = fused K+Q, y1 = V^T.
// ---------------------------------------------------------------------------
__global__ __launch_bounds__(256) void qkv_kernel(
    const float* __restrict__ att, const float* __restrict__ x,
    const float* __restrict__ Wk, const float* __restrict__ bk,
    const float* __restrict__ Wq, const float* __restrict__ bq,
    const float* __restrict__ Wv, const float* __restrict__ bv)
{
#if USE_TC
    extern __shared__ unsigned char dyn_raw[];
    unsigned char* base = (unsigned char*)((((uintptr_t)dyn_raw) + 1023) & ~(uintptr_t)1023);
    unsigned char* Ah[2] = { base,         base + 16384 };
    unsigned char* Al[2] = { base + 32768, base + 49152 };
    unsigned char* B0H[2] = { base + 65536,  base + 81920 };
    unsigned char* B0L[2] = { base + 98304,  base + 114688 };
    unsigned char* B1H[2] = { base + 131072, base + 147456 };
    unsigned char* B1L[2] = { base + 163840, base + 180224 };

    __shared__ uint32_t s_tmem;
    __shared__ __align__(8) unsigned long long s_mbar;

    const bool fused = (blockIdx.y == 0);
    const int m0    = blockIdx.x * 128;
    const int blob  = blockIdx.x;
    const int tid   = threadIdx.x;
    const int wid   = tid / 32;
    const int lane  = tid % 32;

    const float* Asrc = fused ? att : x;
    const unsigned char* w0H = fused ? g_WTimg[0][0] : g_WTimg[2][0];
    const unsigned char* w0L = fused ? g_WTimg[0][1] : g_WTimg[2][1];
    const unsigned char* w1H = g_WTimg[1][0];
    const unsigned char* w1L = g_WTimg[1][1];

    if (wid == 0)
        asm volatile("tcgen05.alloc.cta_group::1.sync.aligned.shared::cta.b32 [%0], %1;"
                     :: "r"(smem_u32(&s_tmem)), "r"(256u) : "memory");
    if (tid == 0) mbar_init(smem_u32(&s_mbar), 1);
    __syncthreads();
    const uint32_t tmem = s_tmem;
    const uint32_t mbar = smem_u32(&s_mbar);

    const int a_row = tid >> 1;
    const int a_sg  = (tid & 1) * 8;
    auto ldgA = [&](int c, float4 (&r)[8]) {
        const float* src = Asrc + (size_t)(m0 + a_row) * DD + c * 64 + a_sg * 4;
#pragma unroll
        for (int i = 0; i < 8; i++) r[i] = *(const float4*)(src + i * 4);
    };
    auto convA = [&](int buf, float4 (&r)[8]) {
#pragma unroll
        for (int i = 0; i < 8; i++) {
            const float4 v = r[i];
            uint2 hv, lv;
            hv.x = prmt_hi(v.x, v.y); hv.y = prmt_hi(v.z, v.w);
            lv.x = pack2(v.x - truncbf(v.x), v.y - truncbf(v.y));
            lv.y = pack2(v.z - truncbf(v.z), v.w - truncbf(v.w));
            const int off = cimg_swz(a_row, (a_sg + i) * 4);
            *(uint2*)(Ah[buf] + off) = hv;
            *(uint2*)(Al[buf] + off) = lv;
        }
    };
    auto loadB = [&](int c, int buf) {
        const int cb = c * 16384;
#pragma unroll
        for (int i = 0; i < 4; i++) {
            const int off = tid * 16 + i * 4096;
            cp_async16(B0H[buf] + off, w0H + cb + off);
            cp_async16(B0L[buf] + off, w0L + cb + off);
            if (fused) {
                cp_async16(B1H[buf] + off, w1H + cb + off);
                cp_async16(B1L[buf] + off, w1L + cb + off);
            }
        }
        CP_COMMIT();
    };
    auto issueMMA = [&](int c, int buf) {
        const uint64_t aH = mkdesc(Ah[buf]), aL = mkdesc(Al[buf]);
        const uint64_t k0H = mkdesc(B0H[buf]), k0L = mkdesc(B0L[buf]);
        if (fused) {
            const uint64_t k1H = mkdesc(B1H[buf]), k1L = mkdesc(B1L[buf]);
#pragma unroll
            for (int p = 0; p < 3; p++) {
                const uint64_t a  = (p == 1) ? aL : aH;
                const uint64_t bK = (p == 2) ? k0L : k0H;
                const uint64_t bQ = (p == 2) ? k1L : k1H;
#pragma unroll
                for (int k = 0; k < 4; k++) {
                    const uint32_t en = (c == 0 && p == 0 && k == 0) ? 0u : 1u;
                    mma_ss(tmem +   0, a + k * 2, bK + k * 2, MMA_IDESC, en);
                    mma_ss(tmem + 128, a + k * 2, bQ + k * 2, MMA_IDESC, en);
                }
            }
        } else {
#pragma unroll
            for (int p = 0; p < 3; p++) {
                const uint64_t a = (p == 2) ? k0L : k0H;
                const uint64_t b = (p == 1) ? aL : aH;
#pragma unroll
                for (int k = 0; k < 4; k++)
                    mma_ss(tmem, a + k * 2, b + k * 2, MMA_IDESC,
                           (c == 0 && p == 0 && k == 0) ? 0u : 1u);
            }
        }
        tc_commit(mbar);
    };

    float4 ra0[8], ra1[8];
    int ph = 0;

    // prologue: conv(0) ready; B(0) in flight
    ldgA(0, ra0);
    ldgA(1, ra1);
    loadB(0, 0);
    convA(0, ra0);
    FENCE_PROXY();
    __syncthreads();

    // iter c: wait MMA(c-1) (per-thread); loadB(c+1); ensure B(c);
    //         ONE sync; issue MMA(c); ldgA(c+2); conv(c+1)+fence.
    auto step = [&](int c, float4 (&rload)[8], float4 (&rconv)[8]) {
        const int buf = c & 1;
        if (c >= 1) { mbar_wait(mbar, ph & 1); ph++; }
        if (c + 1 < 16) loadB(c + 1, buf ^ 1);
        if (c + 1 < 16) { CP_WAIT1(); } else { CP_WAIT0(); }
        __syncthreads();     // gates commit(c): all threads past wait(c-1)
        if (wid == 0 && elect1()) issueMMA(c, buf);
        if (c + 2 < 16) ldgA(c + 2, rload);
        if (c + 1 < 16) {
            convA(buf ^ 1, rconv);
            FENCE_PROXY();
        }
    };

#pragma unroll 1
    for (int cc = 0; cc < 8; cc++) {
        step(2 * cc,     ra0, ra1);
        step(2 * cc + 1, ra1, ra0);
    }
    mbar_wait(mbar, ph & 1); ph++;     // MMA(15)
    TC_FENCE_AFTER();

    const int row     = (wid & 3) * 32 + lane;
    const int half    = (wid >= 4) ? 1 : 0;
    const int colhalf = half * 64;

    auto write_img = [&](unsigned char* oH, unsigned char* oL, float (&d)[64]) {
#pragma unroll
        for (int cch = 0; cch < 8; cch++) {
            const float* sp = &d[8 * cch];
            uint4 hv, lv;
            hv.x = prmt_hi(sp[0], sp[1]); hv.y = prmt_hi(sp[2], sp[3]);
            hv.z = prmt_hi(sp[4], sp[5]); hv.w = prmt_hi(sp[6], sp[7]);
            lv.x = pack2(sp[0] - truncbf(sp[0]), sp[1] - truncbf(sp[1]));
            lv.y = pack2(sp[2] - truncbf(sp[2]), sp[3] - truncbf(sp[3]));
            lv.z = pack2(sp[4] - truncbf(sp[4]), sp[5] - truncbf(sp[5]));
            lv.w = pack2(sp[6] - truncbf(sp[6]), sp[7] - truncbf(sp[7]));
            const int off = img_swz(row, colhalf + 8 * cch);
            *(uint4*)(oH + off) = hv;
            *(uint4*)(oL + off) = lv;
        }
    };

    if (fused) {
        float dk[64], dq[64];
        LDTM32((uint32_t*)&dk[0],  tmem + colhalf);
        LDTM32((uint32_t*)&dk[32], tmem + colhalf + 32);
        LDTM32((uint32_t*)&dq[0],  tmem + 128 + colhalf);
        LDTM32((uint32_t*)&dq[32], tmem + 128 + colhalf + 32);
        TC_WAIT_LD();
        TC_FENCE_BEFORE();
        const float sc = 16.322231186864473f;   // sqrt(128)*log2(e)
#pragma unroll
        for (int j = 0; j < 64; j++) {
            dk[j] = dk[j] + bk[colhalf + j];
            dq[j] = (dq[j] + bq[colhalf + j]) * sc;
        }
        write_img(g_Kimg[0][blob], g_Kimg[1][blob], dk);
        write_img(g_Qimg[0][blob], g_Qimg[1][blob], dq);
    } else {
        float d[64];
        LDTM32((uint32_t*)&d[0],  tmem + colhalf);
        LDTM32((uint32_t*)&d[32], tmem + colhalf + 32);
        TC_WAIT_LD();
        TC_FENCE_BEFORE();
        const float bv_r = bv[row];
#pragma unroll
        for (int j = 0; j < 64; j++) d[j] += bv_r;
        write_img(g_VTimg[0][blob], g_VTimg[1][blob], d);
    }

    __syncthreads();
    if (tid == 0) mbar_inval(mbar);
    __syncthreads();
    if (wid == 0) {
        asm volatile("tcgen05.relinquish_alloc_permit.cta_group::1.sync.aligned;");
        asm volatile("tcgen05.dealloc.cta_group::1.sync.aligned.b32 %0, %1;" :: "r"(tmem), "r"(256u));
    }

#else  // ---------------- fallback: FFMA QKV (grid (128,2)) ----------------
    extern __shared__ char smem_raw[];
    struct QkvSmemF {
        float As[2][128][20];
        float Ws[2][16][132];
    };
    QkvSmemF& smq = *reinterpret_cast<QkvSmemF*>(smem_raw);
    float (*As)[128][20] = smq.As;
    float (*Ws)[16][132] = smq.Ws;

    const int wlo = (blockIdx.y == 0) ? 0 : 2;
    const int whi = (blockIdx.y == 0) ? 1 : 2;
    for (int which = wlo; which <= whi; which++) {
        __syncthreads();
        const float* A    = (which == 2) ? x  : att;
        const float* W    = (which == 0) ? Wk : (which == 1) ? Wq : Wv;
        const float* bias = (which == 0) ? bk : (which == 1) ? bq : bv;
        float* Out        = (which == 0) ? g_K : (which == 1) ? g_Q : g_V;

        const int tid = threadIdx.x;
        const int tx  = tid % 16;
        const int ty  = tid / 16;
        const int m0  = blockIdx.x * 128;

        float acc[8][8];
#pragma unroll
        for (int i = 0; i < 8; i++)
#pragma unroll
            for (int j = 0; j < 8; j++) acc[i][j] = 0.f;

        const int a_row0 = tid / 4,  a_c40 = tid % 4;
        const int a_row1 = (tid + 256) / 4, a_c41 = (tid + 256) % 4;
        const int w_r0 = tid / 32, w_c0 = tid % 32;
        const int w_r1 = (tid + 256) / 32, w_c1 = (tid + 256) % 32;

        float4 a_ld0, a_ld1, w_ld0, w_ld1;
        a_ld0 = *(const float4*)&A[(size_t)(m0 + a_row0) * DD + a_c40 * 4];
        a_ld1 = *(const float4*)&A[(size_t)(m0 + a_row1) * DD + a_c41 * 4];
        w_ld0 = *(const float4*)&W[(size_t)w_r0 * HH + w_c0 * 4];
        w_ld1 = *(const float4*)&W[(size_t)w_r1 * HH + w_c1 * 4];
        *(float4*)&As[0][a_row0][a_c40 * 4] = a_ld0;
        *(float4*)&As[0][a_row1][a_c41 * 4] = a_ld1;
        *(float4*)&Ws[0][w_r0][w_c0 * 4] = w_ld0;
        *(float4*)&Ws[0][w_r1][w_c1 * 4] = w_ld1;
        __syncthreads();

        for (int it = 0; it < DD / 16; it++) {
            const int cur = it & 1, nxt = cur ^ 1;
            if (it < DD / 16 - 1) {
                const int kt = (it + 1) * 16;
                a_ld0 = *(const float4*)&A[(size_t)(m0 + a_row0) * DD + kt + a_c40 * 4];
                a_ld1 = *(const float4*)&A[(size_t)(m0 + a_row1) * DD + kt + a_c41 * 4];
                w_ld0 = *(const float4*)&W[(size_t)(kt + w_r0) * HH + w_c0 * 4];
                w_ld1 = *(const float4*)&W[(size_t)(kt + w_r1) * HH + w_c1 * 4];
            }
#pragma unroll
            for (int kk4 = 0; kk4 < 4; kk4++) {
                float4 a4[8];
#pragma unroll
                for (int i = 0; i < 8; i++)
                    a4[i] = *(const float4*)&As[cur][ty * 8 + i][kk4 * 4];
#pragma unroll
                for (int kkin = 0; kkin < 4; kkin++) {
                    const int kk = kk4 * 4 + kkin;
                    float4 w0v = *(const float4*)&Ws[cur][kk][tx * 4];
                    float4 w1v = *(const float4*)&Ws[cur][kk][64 + tx * 4];
                    const float* w0f = (const float*)&w0v;
                    const float* w1f = (const float*)&w1v;
#pragma unroll
                    for (int i = 0; i < 8; i++) {
                        const float a = ((const float*)&a4[i])[kkin];
#pragma unroll
                        for (int q = 0; q < 4; q++) {
                            acc[i][q]     += a * w0f[q];
                            acc[i][4 + q] += a * w1f[q];
                        }
                    }
                }
            }
            if (it < DD / 16 - 1) {
                *(float4*)&As[nxt][a_row0][a_c40 * 4] = a_ld0;
                *(float4*)&As[nxt][a_row1][a_c41 * 4] = a_ld1;
                *(float4*)&Ws[nxt][w_r0][w_c0 * 4] = w_ld0;
                *(float4*)&Ws[nxt][w_r1][w_c1 * 4] = w_ld1;
                __syncthreads();
            }
        }

        float4 b0 = *(const float4*)&bias[tx * 4];
        float4 b1 = *(const float4*)&bias[64 + tx * 4];
#pragma unroll
        for (int i = 0; i < 8; i++) {
            float4 o0, o1;
            o0.x = acc[i][0] + b0.x; o0.y = acc[i][1] + b0.y;
            o0.z = acc[i][2] + b0.z; o0.w = acc[i][3] + b0.w;
            o1.x = acc[i][4] + b1.x; o1.y = acc[i][5] + b1.y;
            o1.z = acc[i][6] + b1.z; o1.w = acc[i][7] + b1.w;
            *(float4*)&Out[(size_t)(m0 + ty * 8 + i) * HH + tx * 4]      = o0;
            *(float4*)&Out[(size_t)(m0 + ty * 8 + i) * HH + 64 + tx * 4] = o1;
        }
        __syncthreads();
    }
#endif
}

// ---------------------------------------------------------------------------
// Kernel 2: attention — R14 config (lagged-PV + ex2, 2 syncs/tile).
// ---------------------------------------------------------------------------
__global__ __launch_bounds__(256) void attn_kernel(float* __restrict__ out)
{
#if USE_TC
    extern __shared__ unsigned char dyn_raw[];
    unsigned char* base = (unsigned char*)((((uintptr_t)dyn_raw) + 1023) & ~(uintptr_t)1023);
    unsigned char* sQh = base;
    unsigned char* sQl = base + 32768;
    unsigned char* sKh = base + 65536;
    unsigned char* sKl = base + 98304;
    unsigned char* sVh = base + 131072;
    unsigned char* sVl = base + 163840;

    __shared__ uint32_t s_tmem;
    __shared__ __align__(8) unsigned long long s_mbarS, s_mbarPV;
    __shared__ float redM[128][2];
    __shared__ float redS[128][2];

    const int b   = blockIdx.y;
    const int qt  = blockIdx.x;
    const int tid = threadIdx.x;
    const int wid = tid / 32;
    const int lane = tid % 32;
    const int row = (wid & 3) * 32 + lane;
    const int half = (wid >= 4) ? 1 : 0;
    const int colhalf = half * 64;
    const uint32_t warpoff = (uint32_t)(wid & 3) << 21;
    const int qblob = b * NTILES + qt;

    if (wid == 0)
        asm volatile("tcgen05.alloc.cta_group::1.sync.aligned.shared::cta.b32 [%0], %1;"
                     :: "r"(smem_u32(&s_tmem)), "r"(512u) : "memory");
    if (tid == 0) { mbar_init(smem_u32(&s_mbarS), 1); mbar_init(smem_u32(&s_mbarPV), 1); }
    __syncthreads();
    const uint32_t tmem = s_tmem;
    const uint32_t mbarS = smem_u32(&s_mbarS);
    const uint32_t mbarPV = smem_u32(&s_mbarPV);

    auto loadK_nc = [&](int kb) {
        const unsigned char* g0 = g_Kimg[0][kb];
        const unsigned char* g1 = g_Kimg[1][kb];
#pragma unroll
        for (int r = 0; r < 8; r++) {
            const int off = tid * 16 + r * 4096;
            cp_async16(sKh + off, g0 + off);
            cp_async16(sKl + off, g1 + off);
        }
    };
    auto loadV_nc = [&](int kb) {
        const unsigned char* g0 = g_VTimg[0][kb];
        const unsigned char* g1 = g_VTimg[1][kb];
#pragma unroll
        for (int r = 0; r < 8; r++) {
            const int off = tid * 16 + r * 4096;
            cp_async16(sVh + off, g0 + off);
            cp_async16(sVl + off, g1 + off);
        }
    };

    // prologue: Q + K0, one group
    {
        const unsigned char* gq0 = g_Qimg[0][qblob];
        const unsigned char* gq1 = g_Qimg[1][qblob];
#pragma unroll
        for (int r = 0; r < 8; r++) {
            const int off = tid * 16 + r * 4096;
            cp_async16(sQh + off, gq0 + off);
            cp_async16(sQl + off, gq1 + off);
        }
        loadK_nc(b * NTILES);
        CP_COMMIT();
    }

    const uint64_t dQh = mkdesc(sQh), dQl = mkdesc(sQl);
    const uint64_t dKh = mkdesc(sKh), dKl = mkdesc(sKl);
    const uint64_t dVh = mkdesc(sVh), dVl = mkdesc(sVl);

    auto issueS = [&](int t) {
        const uint32_t dst = tmem + ((t & 1) ? TM_S1 : TM_S0);
#pragma unroll
        for (int p = 0; p < 3; p++) {
            const uint64_t da = (p == 1) ? dQl : dQh;
            const uint64_t db = (p == 2) ? dKl : dKh;
#pragma unroll
            for (int k = 0; k < 8; k++) {
                const int koff = (k < 4) ? k * 2 : 1024 + (k - 4) * 2;
                mma_ss(dst, da + koff, db + koff, MMA_IDESC, (p == 0 && k == 0) ? 0u : 1u);
            }
        }
        tc_commit(mbarS);
    };
    auto issuePV = [&]() {
#pragma unroll
        for (int p = 0; p < 3; p++) {
            const uint32_t abase = tmem + ((p == 1) ? TM_PL : TM_PH);
            const uint64_t db = (p == 2) ? dVl : dVh;
#pragma unroll
            for (int k = 0; k < 8; k++) {
                const int koff = (k < 4) ? k * 2 : 1024 + (k - 4) * 2;
                mma_ts(tmem + TM_PV, abase + k * 8, db + koff, MMA_IDESC,
                       (p == 0 && k == 0) ? 0u : 1u);
            }
        }
        tc_commit(mbarPV);
    };

    float O[64];
#pragma unroll
    for (int j = 0; j < 64; j++) O[j] = 0.f;
    float m_r = -1e30f, l_r = 0.f, corr_prev = 1.f;
    int phS = 0, phPV = 0;

    CP_WAIT0();               // Q + K0 resident
    FENCE_PROXY();
    __syncthreads();
    if (wid == 0 && elect1()) issueS(0);

    for (int t = 0; t < NTILES; t++) {
        mbar_wait(mbarS, phS & 1); phS++;   // S(t) done => PV(t-1) done (queue)

        if (t + 1 < NTILES) loadK_nc(b * NTILES + t + 1);
        loadV_nc(b * NTILES + t);
        CP_COMMIT();

        TC_FENCE_AFTER();
        if (t >= 1) {
            mbar_wait(mbarPV, phPV & 1); phPV++;
            TC_FENCE_AFTER();
            float d[64];
            LDTM32((uint32_t*)&d[0],  tmem + TM_PV + colhalf);
            LDTM32((uint32_t*)&d[32], tmem + TM_PV + colhalf + 32);
            TC_WAIT_LD();
#pragma unroll
            for (int j = 0; j < 64; j++) O[j] = O[j] * corr_prev + d[j];
        }

        float s[64];
        const uint32_t sbase = tmem + ((t & 1) ? TM_S1 : TM_S0) + colhalf;
        LDTM32((uint32_t*)&s[0],  sbase);
        LDTM32((uint32_t*)&s[32], sbase + 32);
        TC_WAIT_LD();

        float mx = s[0];
#pragma unroll
        for (int j = 1; j < 64; j++) mx = fmaxf(mx, s[j]);
        redM[row][half] = mx;
        __syncthreads();                    // sync 1
        const float mtile = fmaxf(redM[row][0], redM[row][1]);
        const float mnew = fmaxf(m_r, mtile);
        const float corr = ex2f(m_r - mnew);
        m_r = mnew;
        float lsum = 0.f;
#pragma unroll
        for (int j = 0; j < 64; j++) {
            const float p = ex2f(s[j] - mnew);
            s[j] = p;
            lsum += p;
        }
        redS[row][half] = lsum;

        uint32_t phx[32], plx[32];
#pragma unroll
        for (int j = 0; j < 32; j++) {
            const float e = s[2 * j], o = s[2 * j + 1];
            phx[j] = prmt_hi(e, o);
            plx[j] = pack2(e - truncbf(e), o - truncbf(o));
        }
        STTM32(tmem + TM_PH + 32 * half + warpoff, phx);
        STTM32(tmem + TM_PL + 32 * half + warpoff, plx);
        TC_WAIT_ST();
        TC_FENCE_BEFORE();

        CP_WAIT0();
        __syncthreads();                    // sync 2
        l_r = l_r * corr + redS[row][0] + redS[row][1];
        corr_prev = corr;

        if (wid == 0 && elect1()) {
            TC_FENCE_AFTER();
            issuePV();
            if (t + 1 < NTILES) issueS(t + 1);
        }
    }

    mbar_wait(mbarPV, phPV & 1); phPV++;
    TC_FENCE_AFTER();
    {
        float d[64];
        LDTM32((uint32_t*)&d[0],  tmem + TM_PV + colhalf);
        LDTM32((uint32_t*)&d[32], tmem + TM_PV + colhalf + 32);
        TC_WAIT_LD();
        TC_FENCE_BEFORE();
#pragma unroll
        for (int j = 0; j < 64; j++) O[j] = O[j] * corr_prev + d[j];
    }

    const float inv = 1.f / l_r;
    const size_t obase = ((size_t)b * TT + (size_t)qt * 128 + row) * HH + colhalf;
#pragma unroll
    for (int j4 = 0; j4 < 16; j4++) {
        float4 o;
        o.x = O[4 * j4 + 0] * inv; o.y = O[4 * j4 + 1] * inv;
        o.z = O[4 * j4 + 2] * inv; o.w = O[4 * j4 + 3] * inv;
        *(float4*)&out[obase + 4 * j4] = o;
    }

    __syncthreads();
    if (tid == 0) { mbar_inval(mbarS); mbar_inval(mbarPV); }
    __syncthreads();
    if (wid == 0) {
        asm volatile("tcgen05.relinquish_alloc_permit.cta_group::1.sync.aligned;");
        asm volatile("tcgen05.dealloc.cta_group::1.sync.aligned.b32 %0, %1;" :: "r"(tmem), "r"(512u));
    }

#else  // ---------------- fallback: fp32 FFMA flash attention ----------------
    extern __shared__ char smem_raw[];
    AttnSmem& sm = *reinterpret_cast<AttnSmem*>(smem_raw);

    const int b  = blockIdx.y;
    const int q0 = blockIdx.x * 128;
    const float scale = 11.313708498984761f;

    const int tid = threadIdx.x;
    const int tx  = tid % 16;
    const int ty  = tid / 16;

    const float* Qg = g_Q + ((size_t)b * TT + q0) * HH;
#pragma unroll
    for (int r = 0; r < 16; r++) {
        const int idx = tid + r * 256;
        const int row = idx / 32, c4 = idx % 32;
        float4 v = *(const float4*)&Qg[(size_t)row * HH + c4 * 4];
        v.x *= scale; v.y *= scale; v.z *= scale; v.w *= scale;
        *(float4*)&sm.Q[row][c4 * 4] = v;
    }

    float O[8][8];
    float m_r[8], l_r[8];
#pragma unroll
    for (int i = 0; i < 8; i++) {
        m_r[i] = -1e30f; l_r[i] = 0.f;
#pragma unroll
        for (int j = 0; j < 8; j++) O[i][j] = 0.f;
    }
    __syncthreads();

    for (int k0 = 0; k0 < TT; k0 += 128) {
        const float* Kg = g_K + ((size_t)b * TT + k0) * HH;
        const float* Vg = g_V + ((size_t)b * TT + k0) * HH;

#pragma unroll
        for (int r = 0; r < 16; r++) {
            const int idx = tid + r * 256;
            const int row = idx / 32, c4 = idx % 32;
            cp_async16(&sm.KP[row][c4 * 4], &Kg[(size_t)row * HH + c4 * 4]);
        }
        CP_COMMIT();
#pragma unroll
        for (int r = 0; r < 16; r++) {
            const int idx = tid + r * 256;
            const int row = idx / 32, c4 = idx % 32;
            cp_async16(&sm.V[row][c4 * 4], &Vg[(size_t)row * HH + c4 * 4]);
        }
        CP_COMMIT();

        CP_WAIT1();
        __syncthreads();

        float s[8][8];
#pragma unroll
        for (int i = 0; i < 8; i++)
#pragma unroll
            for (int j = 0; j < 8; j++) s[i][j] = 0.f;

#pragma unroll 8
        for (int kk4 = 0; kk4 < 32; kk4++) {
            float4 q4[8];
#pragma unroll
            for (int i = 0; i < 8; i++)
                q4[i] = *(const float4*)&sm.Q[ty * 8 + i][kk4 * 4];
#pragma unroll
            for (int j = 0; j < 8; j++) {
                float4 k4 = *(const float4*)&sm.KP[tx + 16 * j][kk4 * 4];
#pragma unroll
                for (int i = 0; i < 8; i++) {
                    s[i][j] += q4[i].x * k4.x + q4[i].y * k4.y
                             + q4[i].z * k4.z + q4[i].w * k4.w;
                }
            }
        }
        __syncthreads();

#pragma unroll
        for (int i = 0; i < 8; i++) {
            float mx = s[i][0];
#pragma unroll
            for (int j = 1; j < 8; j++) mx = fmaxf(mx, s[i][j]);
#pragma unroll
            for (int o = 1; o < 16; o <<= 1)
                mx = fmaxf(mx, __shfl_xor_sync(0xffffffffu, mx, o));
            const float mnew = fmaxf(m_r[i], mx);
            const float corr = __expf(m_r[i] - mnew);
            m_r[i] = mnew;
            float sum = 0.f;
#pragma unroll
            for (int j = 0; j < 8; j++) {
                const float p = __expf(s[i][j] - mnew);
                s[i][j] = p;
                sum += p;
            }
#pragma unroll
            for (int o = 1; o < 16; o <<= 1)
                sum += __shfl_xor_sync(0xffffffffu, sum, o);
            l_r[i] = l_r[i] * corr + sum;
#pragma unroll
            for (int j = 0; j < 8; j++) O[i][j] *= corr;
        }

#pragma unroll
        for (int i = 0; i < 8; i++)
#pragma unroll
            for (int j = 0; j < 8; j++)
                sm.KP[ty * 8 + i][tx + 16 * j] = s[i][j];

        CP_WAIT0();
        __syncthreads();

#pragma unroll 4
        for (int k4 = 0; k4 < 32; k4++) {
            float4 p4[8];
#pragma unroll
            for (int i = 0; i < 8; i++)
                p4[i] = *(const float4*)&sm.KP[ty * 8 + i][k4 * 4];
#pragma unroll
            for (int kk = 0; kk < 4; kk++) {
                const int k = k4 * 4 + kk;
                float4 v0 = *(const float4*)&sm.V[k][tx * 4];
                float4 v1 = *(const float4*)&sm.V[k][64 + tx * 4];
                const float* v0f = (const float*)&v0;
                const float* v1f = (const float*)&v1;
#pragma unroll
                for (int i = 0; i < 8; i++) {
                    const float p = ((const float*)&p4[i])[kk];
#pragma unroll
                    for (int q = 0; q < 4; q++) {
                        O[i][q]     += p * v0f[q];
                        O[i][4 + q] += p * v1f[q];
                    }
                }
            }
        }
        __syncthreads();
    }

#pragma unroll
    for (int i = 0; i < 8; i++) {
        const float inv = 1.f / l_r[i];
        float4 o0, o1;
        o0.x = O[i][0] * inv; o0.y = O[i][1] * inv;
        o0.z = O[i][2] * inv; o0.w = O[i][3] * inv;
        o1.x = O[i][4] * inv; o1.y = O[i][5] * inv;
        o1.z = O[i][6] * inv; o1.w = O[i][7] * inv;
        const size_t base = ((size_t)b * TT + q0 + ty * 8 + i) * HH;
        *(float4*)&out[base + tx * 4]      = o0;
        *(float4*)&out[base + 64 + tx * 4] = o1;
    }
#endif
}

// ---------------------------------------------------------------------------
extern "C" void kernel_launch(void* const* d_in, const int* in_sizes, int n_in,
                              void* d_out, int out_size)
{
    const float* x   = (const float*)d_in[0];
    const float* att = (const float*)d_in[1];
    const float* Wk  = (const float*)d_in[2];
    const float* bk  = (const float*)d_in[3];
    const float* Wq  = (const float*)d_in[4];
    const float* bq  = (const float*)d_in[5];
    const float* Wv  = (const float*)d_in[6];
    const float* bv  = (const float*)d_in[7];
    float* out = (float*)d_out;
    (void)in_sizes; (void)n_in; (void)out_size;

    wconv_kernel<<<dim3(3, 64), 256>>>(Wk, Wq, Wv);

    const int qkv_smem = 196608 + 2048;
    cudaFuncSetAttribute(qkv_kernel,
                         cudaFuncAttributeMaxDynamicSharedMemorySize, qkv_smem);
    qkv_kernel<<<dim3(BB * NTILES, 2), 256, qkv_smem>>>(att, x, Wk, bk, Wq, bq, Wv, bv);

    const int attn_smem = (int)sizeof(AttnSmem);
    cudaFuncSetAttribute(attn_kernel,
                         cudaFuncAttributeMaxDynamicSharedMemorySize, attn_smem);
    attn_kernel<<<dim3(NTILES, BB), 256, attn_smem>>>(out);
}